// round 2
// baseline (speedup 1.0000x reference)
#include <cuda_runtime.h>
#include <cuda_bf16.h>

#define N_NODES 50000
#define N_EDGES 800000

// ---------------- scratch (static device globals; no allocation) -------------
__device__ float g_feat[N_NODES * 128];   // feat of current layer (also holds 64-wide layer3 feat)
__device__ float g_h[N_NODES * 128];      // activations between layers
__device__ float g_el[N_NODES * 4];
__device__ float g_er[N_NODES * 4];
__device__ int   g_rp[N_NODES + 1];

// ---------------- CSR row_ptr from sorted dst --------------------------------
__global__ void rowptr_kernel(const int* __restrict__ dst, int* __restrict__ rp,
                              int n, int e) {
    int i = blockIdx.x * blockDim.x + threadIdx.x;
    if (i > n) return;
    // lower_bound: first idx with dst[idx] >= i
    int lo = 0, hi = e;
    while (lo < hi) {
        int mid = (lo + hi) >> 1;
        if (dst[mid] < i) lo = mid + 1; else hi = mid;
    }
    rp[i] = lo;
}

// ---------------- tiled fp32 GEMM: C[M,NC] = A[M,K] @ B[K,NC] ----------------
template <int K, int NC>
__global__ void gemm_kernel(const float* __restrict__ A, const float* __restrict__ B,
                            float* __restrict__ C, int M) {
    constexpr int BM = 64, BK = 16;
    constexpr int TM = 4, TN = NC / 16;       // 8 (NC=128) or 4 (NC=64)
    __shared__ float As[BK][BM + 4];
    __shared__ float Bs[BK][NC];

    const int tid = threadIdx.x;              // 256 threads
    const int tx = tid & 15, ty = tid >> 4;   // 16x16 thread grid
    const int rowBase = blockIdx.x * BM;

    float acc[TM][TN];
#pragma unroll
    for (int i = 0; i < TM; i++)
#pragma unroll
        for (int j = 0; j < TN; j++) acc[i][j] = 0.f;

    for (int k0 = 0; k0 < K; k0 += BK) {
        // load A tile (64x16) transposed into As
        {
            int ar = tid >> 2;                  // 0..63
            int ac = (tid & 3) * 4;             // 0,4,8,12
            float4 v = make_float4(0.f, 0.f, 0.f, 0.f);
            int row = rowBase + ar;
            if (row < M) v = *reinterpret_cast<const float4*>(A + (size_t)row * K + k0 + ac);
            As[ac + 0][ar] = v.x; As[ac + 1][ar] = v.y;
            As[ac + 2][ar] = v.z; As[ac + 3][ar] = v.w;
        }
        // load B tile (16 x NC)
        {
            constexpr int UNITS = BK * NC / 4;          // float4 units
            constexpr int PER_T = UNITS / 256;          // 2 (NC=128) or 1 (NC=64)
#pragma unroll
            for (int u = 0; u < PER_T; u++) {
                int unit = tid + u * 256;
                int brow = unit / (NC / 4);
                int bcol = (unit % (NC / 4)) * 4;
                float4 v = *reinterpret_cast<const float4*>(B + (size_t)(k0 + brow) * NC + bcol);
                Bs[brow][bcol + 0] = v.x; Bs[brow][bcol + 1] = v.y;
                Bs[brow][bcol + 2] = v.z; Bs[brow][bcol + 3] = v.w;
            }
        }
        __syncthreads();

#pragma unroll
        for (int kk = 0; kk < BK; kk++) {
            float a[TM], b[TN];
#pragma unroll
            for (int i = 0; i < TM; i++) a[i] = As[kk][ty * TM + i];
#pragma unroll
            for (int j = 0; j < TN; j++) b[j] = Bs[kk][tx * TN + j];
#pragma unroll
            for (int i = 0; i < TM; i++)
#pragma unroll
                for (int j = 0; j < TN; j++) acc[i][j] = fmaf(a[i], b[j], acc[i][j]);
        }
        __syncthreads();
    }

#pragma unroll
    for (int i = 0; i < TM; i++) {
        int row = rowBase + ty * TM + i;
        if (row >= M) continue;
#pragma unroll
        for (int j = 0; j < TN; j += 4) {
            float4 v = make_float4(acc[i][j], acc[i][j + 1], acc[i][j + 2], acc[i][j + 3]);
            *reinterpret_cast<float4*>(C + (size_t)row * NC + tx * TN + j) = v;
        }
    }
}

// ---------------- per-node attention logits el/er ----------------------------
template <int H, int D>
__global__ void elr_kernel(const float* __restrict__ feat,
                           const float* __restrict__ al, const float* __restrict__ ar,
                           float* __restrict__ el, float* __restrict__ er, int n) {
    int idx = blockIdx.x * blockDim.x + threadIdx.x;
    if (idx >= n * H) return;
    int node = idx / H, h = idx % H;
    const float4* fp = reinterpret_cast<const float4*>(feat + (size_t)node * H * D + h * D);
    const float4* alp = reinterpret_cast<const float4*>(al + h * D);
    const float4* arp = reinterpret_cast<const float4*>(ar + h * D);
    float sl = 0.f, sr = 0.f;
#pragma unroll
    for (int d = 0; d < D / 4; d++) {
        float4 f = fp[d], a = alp[d], r = arp[d];
        sl += f.x * a.x + f.y * a.y + f.z * a.z + f.w * a.w;
        sr += f.x * r.x + f.y * r.y + f.z * r.z + f.w * r.w;
    }
    el[idx] = sl;
    er[idx] = sr;
}

// ---------------- warp-per-dst-node online-softmax aggregation ---------------
template <int H, int D, bool ELU>
__global__ void aggregate_kernel(const float* __restrict__ feat,
                                 const float* __restrict__ el, const float* __restrict__ er,
                                 const float* __restrict__ bias,
                                 const int* __restrict__ src,
                                 const int* __restrict__ rp,
                                 float* __restrict__ out, int n) {
    constexpr int HD = H * D;
    constexpr int VPL = HD / 32;              // values per lane: 4 or 2
    int warp = (blockIdx.x * blockDim.x + threadIdx.x) >> 5;
    if (warp >= n) return;
    const int lane = threadIdx.x & 31;
    const int head = (lane * VPL) / D;        // H=4: lane/8; H=1: 0

    const float erd = er[(size_t)warp * H + head];
    const int beg = rp[warp], end = rp[warp + 1];

    float m = -1e30f, s = 0.f;
    float acc[VPL];
#pragma unroll
    for (int j = 0; j < VPL; j++) acc[j] = 0.f;

    for (int i = beg; i < end; i++) {
        int sn = __ldg(&src[i]);
        float e = __ldg(&el[(size_t)sn * H + head]) + erd;
        e = e > 0.f ? e : 0.2f * e;           // leaky_relu 0.2
        float mn = fmaxf(m, e);
        float sc = __expf(m - mn);
        float w = __expf(e - mn);
        s = s * sc + w;
        if (VPL == 4) {
            float4 v = __ldg(reinterpret_cast<const float4*>(feat + (size_t)sn * HD) + lane);
            acc[0] = acc[0] * sc + w * v.x;
            acc[1] = acc[1] * sc + w * v.y;
            acc[2] = acc[2] * sc + w * v.z;
            acc[3] = acc[3] * sc + w * v.w;
        } else {
            float2 v = __ldg(reinterpret_cast<const float2*>(feat + (size_t)sn * HD) + lane);
            acc[0] = acc[0] * sc + w * v.x;
            acc[1] = acc[1] * sc + w * v.y;
        }
        m = mn;
    }

    float inv = 1.f / (s + 1e-9f);
#pragma unroll
    for (int j = 0; j < VPL; j++) {
        float v = acc[j] * inv + bias[lane * VPL + j];
        if (ELU) v = v > 0.f ? v : (__expf(v) - 1.f);
        acc[j] = v;
    }
    float* op = out + (size_t)warp * HD + lane * VPL;
    if (VPL == 4) *reinterpret_cast<float4*>(op) = make_float4(acc[0], acc[1], acc[2], acc[3]);
    else          *reinterpret_cast<float2*>(op) = make_float2(acc[0], acc[1]);
}

// ---------------- launcher ---------------------------------------------------
extern "C" void kernel_launch(void* const* d_in, const int* in_sizes, int n_in,
                              void* d_out, int out_size) {
    const float* x   = (const float*)d_in[0];
    const int* src   = (const int*)d_in[1];
    const int* dst   = (const int*)d_in[2];
    const float* W1  = (const float*)d_in[3];
    const float* al1 = (const float*)d_in[4];
    const float* ar1 = (const float*)d_in[5];
    const float* b1  = (const float*)d_in[6];
    const float* W2  = (const float*)d_in[7];
    const float* al2 = (const float*)d_in[8];
    const float* ar2 = (const float*)d_in[9];
    const float* b2  = (const float*)d_in[10];
    const float* W3  = (const float*)d_in[11];
    const float* al3 = (const float*)d_in[12];
    const float* ar3 = (const float*)d_in[13];
    const float* b3  = (const float*)d_in[14];
    float* out = (float*)d_out;

    const int n = N_NODES, e = N_EDGES;

    float *feat, *h, *el, *er;
    int *rp;
    cudaGetSymbolAddress((void**)&feat, g_feat);
    cudaGetSymbolAddress((void**)&h,    g_h);
    cudaGetSymbolAddress((void**)&el,   g_el);
    cudaGetSymbolAddress((void**)&er,   g_er);
    cudaGetSymbolAddress((void**)&rp,   g_rp);

    // CSR row pointers from sorted dst
    rowptr_kernel<<<(n + 1 + 255) / 256, 256>>>(dst, rp, n, e);

    const int gemmGrid = (n + 63) / 64;
    const int aggGrid = (n + 7) / 8;              // 8 warps / block
    const int elrGrid4 = (n * 4 + 255) / 256;
    const int elrGrid1 = (n + 255) / 256;

    // ---- layer 1: x[50000,256] -> feat[50000,128], 4 heads x 32
    gemm_kernel<256, 128><<<gemmGrid, 256>>>(x, W1, feat, n);
    elr_kernel<4, 32><<<elrGrid4, 256>>>(feat, al1, ar1, el, er, n);
    aggregate_kernel<4, 32, true><<<aggGrid, 256>>>(feat, el, er, b1, src, rp, h, n);

    // ---- layer 2: h[50000,128] -> feat[50000,128], 4 heads x 32
    gemm_kernel<128, 128><<<gemmGrid, 256>>>(h, W2, feat, n);
    elr_kernel<4, 32><<<elrGrid4, 256>>>(feat, al2, ar2, el, er, n);
    aggregate_kernel<4, 32, true><<<aggGrid, 256>>>(feat, el, er, b2, src, rp, h, n);

    // ---- layer 3: h[50000,128] -> feat[50000,64], 1 head x 64; mean over 1 head = identity
    gemm_kernel<128, 64><<<gemmGrid, 256>>>(h, W3, feat, n);
    elr_kernel<1, 64><<<elrGrid1, 256>>>(feat, al3, ar3, el, er, n);
    aggregate_kernel<1, 64, false><<<aggGrid, 256>>>(feat, el, er, b3, src, rp, out, n);
}

// round 6
// speedup vs baseline: 1.8484x; 1.8484x over previous
#include <cuda_runtime.h>
#include <cuda_bf16.h>
#include <cstdint>

#define N_NODES 50000
#define N_EDGES 800000

// ---------------- scratch (static device globals; no allocation) -------------
__device__ float g_feat[N_NODES * 128];
__device__ float g_h[N_NODES * 128];
__device__ float g_el[N_NODES * 4];
__device__ float g_er[N_NODES * 4];
__device__ int   g_rp[N_NODES + 1];

// ---------------- helpers ----------------------------------------------------
__device__ __forceinline__ uint32_t f2tf32(float f) {
    uint32_t r;
    asm("cvt.rna.tf32.f32 %0, %1;" : "=r"(r) : "f"(f));
    return r;
}
__device__ __forceinline__ void mma_tf32(float* d, const uint32_t* a, const uint32_t* b) {
    asm volatile(
        "mma.sync.aligned.m16n8k8.row.col.f32.tf32.tf32.f32 "
        "{%0,%1,%2,%3}, {%4,%5,%6,%7}, {%8,%9}, {%0,%1,%2,%3};"
        : "+f"(d[0]), "+f"(d[1]), "+f"(d[2]), "+f"(d[3])
        : "r"(a[0]), "r"(a[1]), "r"(a[2]), "r"(a[3]), "r"(b[0]), "r"(b[1]));
}

// ---------------- CSR row_ptr from sorted dst --------------------------------
__global__ void rowptr_kernel(const int* __restrict__ dst, int* __restrict__ rp,
                              int n, int e) {
    int i = blockIdx.x * blockDim.x + threadIdx.x;
    if (i > n) return;
    int lo = 0, hi = e;
    while (lo < hi) {
        int mid = (lo + hi) >> 1;
        if (dst[mid] < i) lo = mid + 1; else hi = mid;
    }
    rp[i] = lo;
}

// ---------------- tf32 mma.sync GEMM (+ optional fused el/er) ----------------
// C[M,NC] = A[M,K] @ W[K,NC]; FUSE_ELR requires NC=128, H=4, D=32.
// Block: 256 threads = 8 warps (4 row-warps x 2 col-warps). BM=128.
// Warp tile: 32 rows x NC/2 cols. mma m16n8k8 tf32.
template <int K, int NC, bool FUSE>
__global__ void __launch_bounds__(256)
gemm_mma_kernel(const float* __restrict__ A, const float* __restrict__ W,
                const float* __restrict__ al, const float* __restrict__ ar,
                float* __restrict__ C, float* __restrict__ el, float* __restrict__ er,
                int M) {
    constexpr int BM = 128, KC = 32;
    constexpr int WCOLS = NC / 2;              // 64 or 32
    constexpr int RT = 2;                      // 2 x m16 = 32 rows per warp
    constexpr int CT = WCOLS / 8;              // 8 or 4 n8-tiles per warp
    constexpr int APAD = KC + 4;               // 36
    constexpr int WPAD = NC + 4;

    __shared__ uint32_t As[BM][APAD];
    __shared__ uint32_t Ws[KC][WPAD];
    __shared__ float s_al[NC], s_ar[NC];

    const int tid = threadIdx.x;
    const int wid = tid >> 5, lane = tid & 31;
    const int g = lane >> 2, t = lane & 3;     // group / thread-in-group
    const int warpRow = wid >> 1, warpCol = wid & 1;
    const int rowBase = blockIdx.x * BM;

    if (FUSE) {
        if (tid < NC) s_al[tid] = al[tid];
        else if (tid < 2 * NC) s_ar[tid - NC] = ar[tid - NC];
    }

    float acc[RT][CT][4];
#pragma unroll
    for (int i = 0; i < RT; i++)
#pragma unroll
        for (int j = 0; j < CT; j++)
#pragma unroll
            for (int q = 0; q < 4; q++) acc[i][j][q] = 0.f;

    for (int k0 = 0; k0 < K; k0 += KC) {
        if (k0 > 0) __syncthreads();
        // ---- load A chunk (BM x KC), convert to tf32 ----
        {
            constexpr int UNITS = BM * KC / 4;        // 1024
#pragma unroll
            for (int u = tid; u < UNITS; u += 256) {
                int row = u >> 3;                     // /(KC/4)=8
                int c = (u & 7) << 2;
                float4 v = make_float4(0.f, 0.f, 0.f, 0.f);
                int grow = rowBase + row;
                if (grow < M)
                    v = *reinterpret_cast<const float4*>(A + (size_t)grow * K + k0 + c);
                As[row][c + 0] = f2tf32(v.x); As[row][c + 1] = f2tf32(v.y);
                As[row][c + 2] = f2tf32(v.z); As[row][c + 3] = f2tf32(v.w);
            }
        }
        // ---- load W chunk (KC x NC), convert to tf32 ----
        {
            constexpr int UNITS = KC * NC / 4;        // 1024 or 512
#pragma unroll
            for (int u = tid; u < UNITS; u += 256) {
                int k = u / (NC / 4);
                int c = (u % (NC / 4)) << 2;
                float4 v = *reinterpret_cast<const float4*>(W + (size_t)(k0 + k) * NC + c);
                Ws[k][c + 0] = f2tf32(v.x); Ws[k][c + 1] = f2tf32(v.y);
                Ws[k][c + 2] = f2tf32(v.z); Ws[k][c + 3] = f2tf32(v.w);
            }
        }
        __syncthreads();

#pragma unroll
        for (int ks = 0; ks < KC / 8; ks++) {
            const int kk = ks * 8;
            uint32_t afr[RT][4];
#pragma unroll
            for (int rt = 0; rt < RT; rt++) {
                int r0 = warpRow * 32 + rt * 16 + g;
                afr[rt][0] = As[r0][kk + t];
                afr[rt][1] = As[r0 + 8][kk + t];
                afr[rt][2] = As[r0][kk + t + 4];
                afr[rt][3] = As[r0 + 8][kk + t + 4];
            }
            uint32_t bfr[CT][2];
#pragma unroll
            for (int ct = 0; ct < CT; ct++) {
                int n = warpCol * WCOLS + ct * 8 + g;
                bfr[ct][0] = Ws[kk + t][n];
                bfr[ct][1] = Ws[kk + t + 4][n];
            }
#pragma unroll
            for (int rt = 0; rt < RT; rt++)
#pragma unroll
                for (int ct = 0; ct < CT; ct++)
                    mma_tf32(acc[rt][ct], afr[rt], bfr[ct]);
        }
    }

    // ---- write C + fused el/er ----
#pragma unroll
    for (int rt = 0; rt < RT; rt++) {
        int r0 = rowBase + warpRow * 32 + rt * 16 + g;
        int r1 = r0 + 8;
#pragma unroll
        for (int ct = 0; ct < CT; ct++) {
            int col = warpCol * WCOLS + ct * 8 + t * 2;
            if (r0 < M)
                *reinterpret_cast<float2*>(C + (size_t)r0 * NC + col) =
                    make_float2(acc[rt][ct][0], acc[rt][ct][1]);
            if (r1 < M)
                *reinterpret_cast<float2*>(C + (size_t)r1 * NC + col) =
                    make_float2(acc[rt][ct][2], acc[rt][ct][3]);
        }
        if (FUSE) {
            // NC=128, H=4, D=32: warp strip = heads {2*warpCol, 2*warpCol+1}
#pragma unroll
            for (int hh = 0; hh < 2; hh++) {
                float sl0 = 0.f, sr0 = 0.f, sl1 = 0.f, sr1 = 0.f;
#pragma unroll
                for (int ct = hh * (CT / 2); ct < (hh + 1) * (CT / 2); ct++) {
                    int col = warpCol * WCOLS + ct * 8 + t * 2;
#pragma unroll
                    for (int j = 0; j < 2; j++) {
                        float a_l = s_al[col + j], a_r = s_ar[col + j];
                        sl0 = fmaf(acc[rt][ct][j], a_l, sl0);
                        sr0 = fmaf(acc[rt][ct][j], a_r, sr0);
                        sl1 = fmaf(acc[rt][ct][2 + j], a_l, sl1);
                        sr1 = fmaf(acc[rt][ct][2 + j], a_r, sr1);
                    }
                }
                // reduce over the 4 threads of the quad (lanes differ in bits 0-1)
#pragma unroll
                for (int d = 1; d < 4; d <<= 1) {
                    sl0 += __shfl_xor_sync(0xFFFFFFFF, sl0, d);
                    sr0 += __shfl_xor_sync(0xFFFFFFFF, sr0, d);
                    sl1 += __shfl_xor_sync(0xFFFFFFFF, sl1, d);
                    sr1 += __shfl_xor_sync(0xFFFFFFFF, sr1, d);
                }
                if (t == 0) {
                    int head = warpCol * 2 + hh;
                    if (r0 < M) { el[(size_t)r0 * 4 + head] = sl0; er[(size_t)r0 * 4 + head] = sr0; }
                    if (r1 < M) { el[(size_t)r1 * 4 + head] = sl1; er[(size_t)r1 * 4 + head] = sr1; }
                }
            }
        }
    }
}

// ---------------- per-node attention logits el/er (layer 3 only) -------------
template <int H, int D>
__global__ void elr_kernel(const float* __restrict__ feat,
                           const float* __restrict__ al, const float* __restrict__ ar,
                           float* __restrict__ el, float* __restrict__ er, int n) {
    int idx = blockIdx.x * blockDim.x + threadIdx.x;
    if (idx >= n * H) return;
    int node = idx / H, h = idx % H;
    const float4* fp = reinterpret_cast<const float4*>(feat + (size_t)node * H * D + h * D);
    const float4* alp = reinterpret_cast<const float4*>(al + h * D);
    const float4* arp = reinterpret_cast<const float4*>(ar + h * D);
    float sl = 0.f, sr = 0.f;
#pragma unroll
    for (int d = 0; d < D / 4; d++) {
        float4 f = fp[d], a = alp[d], r = arp[d];
        sl += f.x * a.x + f.y * a.y + f.z * a.z + f.w * a.w;
        sr += f.x * r.x + f.y * r.y + f.z * r.z + f.w * r.w;
    }
    el[idx] = sl;
    er[idx] = sr;
}

// ---------------- warp-per-dst-node online-softmax aggregation ---------------
template <int H, int D, bool ELU>
__global__ void aggregate_kernel(const float* __restrict__ feat,
                                 const float* __restrict__ el, const float* __restrict__ er,
                                 const float* __restrict__ bias,
                                 const int* __restrict__ src,
                                 const int* __restrict__ rp,
                                 float* __restrict__ out, int n) {
    constexpr int HD = H * D;
    constexpr int VPL = HD / 32;
    int warp = (blockIdx.x * blockDim.x + threadIdx.x) >> 5;
    if (warp >= n) return;
    const int lane = threadIdx.x & 31;
    const int head = (lane * VPL) / D;

    const float erd = er[(size_t)warp * H + head];
    const int beg = rp[warp], end = rp[warp + 1];

    float m = -1e30f, s = 0.f;
    float acc[VPL];
#pragma unroll
    for (int j = 0; j < VPL; j++) acc[j] = 0.f;

    for (int i = beg; i < end; i++) {
        int sn = __ldg(&src[i]);
        float e = __ldg(&el[(size_t)sn * H + head]) + erd;
        e = e > 0.f ? e : 0.2f * e;
        float mn = fmaxf(m, e);
        float sc = __expf(m - mn);
        float w = __expf(e - mn);
        s = s * sc + w;
        if (VPL == 4) {
            float4 v = __ldg(reinterpret_cast<const float4*>(feat + (size_t)sn * HD) + lane);
            acc[0] = acc[0] * sc + w * v.x;
            acc[1] = acc[1] * sc + w * v.y;
            acc[2] = acc[2] * sc + w * v.z;
            acc[3] = acc[3] * sc + w * v.w;
        } else {
            float2 v = __ldg(reinterpret_cast<const float2*>(feat + (size_t)sn * HD) + lane);
            acc[0] = acc[0] * sc + w * v.x;
            acc[1] = acc[1] * sc + w * v.y;
        }
        m = mn;
    }

    float inv = 1.f / (s + 1e-9f);
#pragma unroll
    for (int j = 0; j < VPL; j++) {
        float v = acc[j] * inv + bias[lane * VPL + j];
        if (ELU) v = v > 0.f ? v : (__expf(v) - 1.f);
        acc[j] = v;
    }
    float* op = out + (size_t)warp * HD + lane * VPL;
    if (VPL == 4) *reinterpret_cast<float4*>(op) = make_float4(acc[0], acc[1], acc[2], acc[3]);
    else          *reinterpret_cast<float2*>(op) = make_float2(acc[0], acc[1]);
}

// ---------------- launcher ---------------------------------------------------
extern "C" void kernel_launch(void* const* d_in, const int* in_sizes, int n_in,
                              void* d_out, int out_size) {
    const float* x   = (const float*)d_in[0];
    const int* src   = (const int*)d_in[1];
    const int* dst   = (const int*)d_in[2];
    const float* W1  = (const float*)d_in[3];
    const float* al1 = (const float*)d_in[4];
    const float* ar1 = (const float*)d_in[5];
    const float* b1  = (const float*)d_in[6];
    const float* W2  = (const float*)d_in[7];
    const float* al2 = (const float*)d_in[8];
    const float* ar2 = (const float*)d_in[9];
    const float* b2  = (const float*)d_in[10];
    const float* W3  = (const float*)d_in[11];
    const float* al3 = (const float*)d_in[12];
    const float* ar3 = (const float*)d_in[13];
    const float* b3  = (const float*)d_in[14];
    float* out = (float*)d_out;

    const int n = N_NODES, e = N_EDGES;

    float *feat, *h, *el, *er;
    int *rp;
    cudaGetSymbolAddress((void**)&feat, g_feat);
    cudaGetSymbolAddress((void**)&h,    g_h);
    cudaGetSymbolAddress((void**)&el,   g_el);
    cudaGetSymbolAddress((void**)&er,   g_er);
    cudaGetSymbolAddress((void**)&rp,   g_rp);

    rowptr_kernel<<<(n + 1 + 255) / 256, 256>>>(dst, rp, n, e);

    const int gemmGrid = (n + 127) / 128;   // 391
    const int aggGrid = (n + 7) / 8;
    const int elrGrid1 = (n + 255) / 256;

    // ---- layer 1: x[50000,256] -> feat[50000,128], elr fused
    gemm_mma_kernel<256, 128, true><<<gemmGrid, 256>>>(x, W1, al1, ar1, feat, el, er, n);
    aggregate_kernel<4, 32, true><<<aggGrid, 256>>>(feat, el, er, b1, src, rp, h, n);

    // ---- layer 2
    gemm_mma_kernel<128, 128, true><<<gemmGrid, 256>>>(h, W2, al2, ar2, feat, el, er, n);
    aggregate_kernel<4, 32, true><<<aggGrid, 256>>>(feat, el, er, b2, src, rp, h, n);

    // ---- layer 3: 1 head x 64; elr separate (head spans both col-warps)
    gemm_mma_kernel<128, 64, false><<<gemmGrid, 256>>>(h, W3, nullptr, nullptr, feat, el, er, n);
    elr_kernel<1, 64><<<elrGrid1, 256>>>(feat, al3, ar3, el, er, n);
    aggregate_kernel<1, 64, false><<<aggGrid, 256>>>(feat, el, er, b3, src, rp, out, n);
}

// round 11
// speedup vs baseline: 1.9447x; 1.0521x over previous
#include <cuda_runtime.h>
#include <cuda_bf16.h>
#include <cstdint>

#define N_NODES 50000
#define N_EDGES 800000

// ---------------- scratch (static device globals; no allocation) -------------
__device__ float g_feat[N_NODES * 128];
__device__ float g_h[N_NODES * 128];
__device__ float g_el[N_NODES * 4];
__device__ float g_er[N_NODES * 4];
__device__ int   g_rp[N_NODES + 1];

// ---------------- helpers ----------------------------------------------------
__device__ __forceinline__ uint32_t f2tf32(float f) {
    uint32_t r;
    asm("cvt.rna.tf32.f32 %0, %1;" : "=r"(r) : "f"(f));
    return r;
}
__device__ __forceinline__ void mma_tf32(float* d, const uint32_t* a, const uint32_t* b) {
    asm volatile(
        "mma.sync.aligned.m16n8k8.row.col.f32.tf32.tf32.f32 "
        "{%0,%1,%2,%3}, {%4,%5,%6,%7}, {%8,%9}, {%0,%1,%2,%3};"
        : "+f"(d[0]), "+f"(d[1]), "+f"(d[2]), "+f"(d[3])
        : "r"(a[0]), "r"(a[1]), "r"(a[2]), "r"(a[3]), "r"(b[0]), "r"(b[1]));
}

// ---------------- CSR row_ptr from sorted dst --------------------------------
__global__ void rowptr_kernel(const int* __restrict__ dst, int* __restrict__ rp,
                              int n, int e) {
    int i = blockIdx.x * blockDim.x + threadIdx.x;
    if (i > n) return;
    int lo = 0, hi = e;
    while (lo < hi) {
        int mid = (lo + hi) >> 1;
        if (dst[mid] < i) lo = mid + 1; else hi = mid;
    }
    rp[i] = lo;
}

// ---------------- tf32 mma.sync GEMM (+ optional fused el/er) ----------------
// C[M,NC] = A[M,K] @ W[K,NC]; FUSE requires NC=128, H=4, D=32.
// 512 threads = 16 warps as 4 row-warps x 4 col-warps. BM=128.
// Warp tile: 32 rows x NC/4 cols.
template <int K, int NC, bool FUSE>
__global__ void __launch_bounds__(512)
gemm_mma_kernel(const float* __restrict__ A, const float* __restrict__ W,
                const float* __restrict__ al, const float* __restrict__ ar,
                float* __restrict__ C, float* __restrict__ el, float* __restrict__ er,
                int M) {
    constexpr int BM = 128, KC = 32;
    constexpr int WCOLS = NC / 4;              // 32 or 16
    constexpr int RT = 2;                      // 2 x m16 = 32 rows per warp
    constexpr int CT = WCOLS / 8;              // 4 or 2 n8-tiles per warp
    constexpr int APAD = KC + 4;               // 36
    constexpr int WPAD = NC + 4;

    __shared__ uint32_t As[BM][APAD];
    __shared__ uint32_t Ws[KC][WPAD];
    __shared__ float s_al[NC], s_ar[NC];

    const int tid = threadIdx.x;
    const int wid = tid >> 5, lane = tid & 31;
    const int g = lane >> 2, t = lane & 3;     // group / thread-in-group
    const int warpRow = wid >> 2, warpCol = wid & 3;
    const int rowBase = blockIdx.x * BM;

    if (FUSE) {
        if (tid < NC) s_al[tid] = al[tid];
        else if (tid < 2 * NC) s_ar[tid - NC] = ar[tid - NC];
    }

    float acc[RT][CT][4];
#pragma unroll
    for (int i = 0; i < RT; i++)
#pragma unroll
        for (int j = 0; j < CT; j++)
#pragma unroll
            for (int q = 0; q < 4; q++) acc[i][j][q] = 0.f;

    for (int k0 = 0; k0 < K; k0 += KC) {
        if (k0 > 0) __syncthreads();
        // ---- load A chunk (BM x KC), convert to tf32 ----
        {
            constexpr int UNITS = BM * KC / 4;        // 1024
#pragma unroll
            for (int u = tid; u < UNITS; u += 512) {
                int row = u >> 3;                     // /(KC/4)=8
                int c = (u & 7) << 2;
                float4 v = make_float4(0.f, 0.f, 0.f, 0.f);
                int grow = rowBase + row;
                if (grow < M)
                    v = *reinterpret_cast<const float4*>(A + (size_t)grow * K + k0 + c);
                As[row][c + 0] = f2tf32(v.x); As[row][c + 1] = f2tf32(v.y);
                As[row][c + 2] = f2tf32(v.z); As[row][c + 3] = f2tf32(v.w);
            }
        }
        // ---- load W chunk (KC x NC), convert to tf32 ----
        {
            constexpr int UNITS = KC * NC / 4;        // 1024 or 512
#pragma unroll
            for (int u = tid; u < UNITS; u += 512) {
                int k = u / (NC / 4);
                int c = (u % (NC / 4)) << 2;
                float4 v = *reinterpret_cast<const float4*>(W + (size_t)(k0 + k) * NC + c);
                Ws[k][c + 0] = f2tf32(v.x); Ws[k][c + 1] = f2tf32(v.y);
                Ws[k][c + 2] = f2tf32(v.z); Ws[k][c + 3] = f2tf32(v.w);
            }
        }
        __syncthreads();

#pragma unroll
        for (int ks = 0; ks < KC / 8; ks++) {
            const int kk = ks * 8;
            uint32_t afr[RT][4];
#pragma unroll
            for (int rt = 0; rt < RT; rt++) {
                int r0 = warpRow * 32 + rt * 16 + g;
                afr[rt][0] = As[r0][kk + t];
                afr[rt][1] = As[r0 + 8][kk + t];
                afr[rt][2] = As[r0][kk + t + 4];
                afr[rt][3] = As[r0 + 8][kk + t + 4];
            }
            uint32_t bfr[CT][2];
#pragma unroll
            for (int ct = 0; ct < CT; ct++) {
                int n = warpCol * WCOLS + ct * 8 + g;
                bfr[ct][0] = Ws[kk + t][n];
                bfr[ct][1] = Ws[kk + t + 4][n];
            }
#pragma unroll
            for (int rt = 0; rt < RT; rt++)
#pragma unroll
                for (int ct = 0; ct < CT; ct++)
                    mma_tf32(acc[rt][ct], afr[rt], bfr[ct]);
        }
    }

    // ---- write C + fused el/er ----
#pragma unroll
    for (int rt = 0; rt < RT; rt++) {
        int r0 = rowBase + warpRow * 32 + rt * 16 + g;
        int r1 = r0 + 8;
#pragma unroll
        for (int ct = 0; ct < CT; ct++) {
            int col = warpCol * WCOLS + ct * 8 + t * 2;
            if (r0 < M)
                *reinterpret_cast<float2*>(C + (size_t)r0 * NC + col) =
                    make_float2(acc[rt][ct][0], acc[rt][ct][1]);
            if (r1 < M)
                *reinterpret_cast<float2*>(C + (size_t)r1 * NC + col) =
                    make_float2(acc[rt][ct][2], acc[rt][ct][3]);
        }
        if (FUSE) {
            // NC=128, H=4, D=32, WC=4: warp strip (32 cols) == head warpCol
            float sl0 = 0.f, sr0 = 0.f, sl1 = 0.f, sr1 = 0.f;
#pragma unroll
            for (int ct = 0; ct < CT; ct++) {
                int col = warpCol * WCOLS + ct * 8 + t * 2;
#pragma unroll
                for (int j = 0; j < 2; j++) {
                    float a_l = s_al[col + j], a_r = s_ar[col + j];
                    sl0 = fmaf(acc[rt][ct][j], a_l, sl0);
                    sr0 = fmaf(acc[rt][ct][j], a_r, sr0);
                    sl1 = fmaf(acc[rt][ct][2 + j], a_l, sl1);
                    sr1 = fmaf(acc[rt][ct][2 + j], a_r, sr1);
                }
            }
#pragma unroll
            for (int d = 1; d < 4; d <<= 1) {
                sl0 += __shfl_xor_sync(0xFFFFFFFF, sl0, d);
                sr0 += __shfl_xor_sync(0xFFFFFFFF, sr0, d);
                sl1 += __shfl_xor_sync(0xFFFFFFFF, sl1, d);
                sr1 += __shfl_xor_sync(0xFFFFFFFF, sr1, d);
            }
            if (t == 0) {
                int head = warpCol;
                if (r0 < M) { el[(size_t)r0 * 4 + head] = sl0; er[(size_t)r0 * 4 + head] = sr0; }
                if (r1 < M) { el[(size_t)r1 * 4 + head] = sl1; er[(size_t)r1 * 4 + head] = sr1; }
            }
        }
    }
}

// ---------------- per-node attention logits el/er (layer 3 only) -------------
template <int H, int D>
__global__ void elr_kernel(const float* __restrict__ feat,
                           const float* __restrict__ al, const float* __restrict__ ar,
                           float* __restrict__ el, float* __restrict__ er, int n) {
    int idx = blockIdx.x * blockDim.x + threadIdx.x;
    if (idx >= n * H) return;
    int node = idx / H, h = idx % H;
    const float4* fp = reinterpret_cast<const float4*>(feat + (size_t)node * H * D + h * D);
    const float4* alp = reinterpret_cast<const float4*>(al + h * D);
    const float4* arp = reinterpret_cast<const float4*>(ar + h * D);
    float sl = 0.f, sr = 0.f;
#pragma unroll
    for (int d = 0; d < D / 4; d++) {
        float4 f = fp[d], a = alp[d], r = arp[d];
        sl += f.x * a.x + f.y * a.y + f.z * a.z + f.w * a.w;
        sr += f.x * r.x + f.y * r.y + f.z * r.z + f.w * r.w;
    }
    el[idx] = sl;
    er[idx] = sr;
}

// ---------------- warp-per-dst-node softmax aggregation (no-max, unrolled) ---
// Logits are structurally bounded (|e| ~ 3), so exp() without max-subtraction is
// safe; alpha differs from reference only via the 1e-9 denominator eps (~1e-9 rel).
template <int H, int D, bool ELU>
__global__ void aggregate_kernel(const float* __restrict__ feat,
                                 const float* __restrict__ el, const float* __restrict__ er,
                                 const float* __restrict__ bias,
                                 const int* __restrict__ src,
                                 const int* __restrict__ rp,
                                 float* __restrict__ out, int n) {
    constexpr int HD = H * D;
    constexpr int VPL = HD / 32;              // 4 (H=4) or 2 (H=1)
    int warp = (blockIdx.x * blockDim.x + threadIdx.x) >> 5;
    if (warp >= n) return;
    const int lane = threadIdx.x & 31;
    const int head = (lane * VPL) / D;

    const float erd = er[(size_t)warp * H + head];
    const int beg = rp[warp], end = rp[warp + 1];

    float s = 0.f;
    float acc[VPL];
#pragma unroll
    for (int j = 0; j < VPL; j++) acc[j] = 0.f;

    int i = beg;
    for (; i + 2 <= end; i += 2) {
        int sn0 = __ldg(&src[i]);
        int sn1 = __ldg(&src[i + 1]);
        float e0 = __ldg(&el[(size_t)sn0 * H + head]) + erd;
        float e1 = __ldg(&el[(size_t)sn1 * H + head]) + erd;
        e0 = e0 > 0.f ? e0 : 0.2f * e0;
        e1 = e1 > 0.f ? e1 : 0.2f * e1;
        float w0 = __expf(e0);
        float w1 = __expf(e1);
        if (VPL == 4) {
            float4 v0 = __ldg(reinterpret_cast<const float4*>(feat + (size_t)sn0 * HD) + lane);
            float4 v1 = __ldg(reinterpret_cast<const float4*>(feat + (size_t)sn1 * HD) + lane);
            acc[0] = fmaf(w0, v0.x, fmaf(w1, v1.x, acc[0]));
            acc[1] = fmaf(w0, v0.y, fmaf(w1, v1.y, acc[1]));
            acc[2] = fmaf(w0, v0.z, fmaf(w1, v1.z, acc[2]));
            acc[3] = fmaf(w0, v0.w, fmaf(w1, v1.w, acc[3]));
        } else {
            float2 v0 = __ldg(reinterpret_cast<const float2*>(feat + (size_t)sn0 * HD) + lane);
            float2 v1 = __ldg(reinterpret_cast<const float2*>(feat + (size_t)sn1 * HD) + lane);
            acc[0] = fmaf(w0, v0.x, fmaf(w1, v1.x, acc[0]));
            acc[1] = fmaf(w0, v0.y, fmaf(w1, v1.y, acc[1]));
        }
        s += w0 + w1;
    }
    if (i < end) {
        int sn = __ldg(&src[i]);
        float e = __ldg(&el[(size_t)sn * H + head]) + erd;
        e = e > 0.f ? e : 0.2f * e;
        float w = __expf(e);
        if (VPL == 4) {
            float4 v = __ldg(reinterpret_cast<const float4*>(feat + (size_t)sn * HD) + lane);
            acc[0] = fmaf(w, v.x, acc[0]);
            acc[1] = fmaf(w, v.y, acc[1]);
            acc[2] = fmaf(w, v.z, acc[2]);
            acc[3] = fmaf(w, v.w, acc[3]);
        } else {
            float2 v = __ldg(reinterpret_cast<const float2*>(feat + (size_t)sn * HD) + lane);
            acc[0] = fmaf(w, v.x, acc[0]);
            acc[1] = fmaf(w, v.y, acc[1]);
        }
        s += w;
    }

    float inv = 1.f / (s + 1e-9f);
#pragma unroll
    for (int j = 0; j < VPL; j++) {
        float v = acc[j] * inv + bias[lane * VPL + j];
        if (ELU) v = v > 0.f ? v : (__expf(v) - 1.f);
        acc[j] = v;
    }
    float* op = out + (size_t)warp * HD + lane * VPL;
    if (VPL == 4) *reinterpret_cast<float4*>(op) = make_float4(acc[0], acc[1], acc[2], acc[3]);
    else          *reinterpret_cast<float2*>(op) = make_float2(acc[0], acc[1]);
}

// ---------------- launcher ---------------------------------------------------
extern "C" void kernel_launch(void* const* d_in, const int* in_sizes, int n_in,
                              void* d_out, int out_size) {
    const float* x   = (const float*)d_in[0];
    const int* src   = (const int*)d_in[1];
    const int* dst   = (const int*)d_in[2];
    const float* W1  = (const float*)d_in[3];
    const float* al1 = (const float*)d_in[4];
    const float* ar1 = (const float*)d_in[5];
    const float* b1  = (const float*)d_in[6];
    const float* W2  = (const float*)d_in[7];
    const float* al2 = (const float*)d_in[8];
    const float* ar2 = (const float*)d_in[9];
    const float* b2  = (const float*)d_in[10];
    const float* W3  = (const float*)d_in[11];
    const float* al3 = (const float*)d_in[12];
    const float* ar3 = (const float*)d_in[13];
    const float* b3  = (const float*)d_in[14];
    float* out = (float*)d_out;

    const int n = N_NODES, e = N_EDGES;

    float *feat, *h, *el, *er;
    int *rp;
    cudaGetSymbolAddress((void**)&feat, g_feat);
    cudaGetSymbolAddress((void**)&h,    g_h);
    cudaGetSymbolAddress((void**)&el,   g_el);
    cudaGetSymbolAddress((void**)&er,   g_er);
    cudaGetSymbolAddress((void**)&rp,   g_rp);

    rowptr_kernel<<<(n + 1 + 255) / 256, 256>>>(dst, rp, n, e);

    const int gemmGrid = (n + 127) / 128;   // 391
    const int aggGrid = (n + 7) / 8;
    const int elrGrid1 = (n + 255) / 256;

    // ---- layer 1: x[50000,256] -> feat[50000,128], elr fused
    gemm_mma_kernel<256, 128, true><<<gemmGrid, 512>>>(x, W1, al1, ar1, feat, el, er, n);
    aggregate_kernel<4, 32, true><<<aggGrid, 256>>>(feat, el, er, b1, src, rp, h, n);

    // ---- layer 2
    gemm_mma_kernel<128, 128, true><<<gemmGrid, 512>>>(h, W2, al2, ar2, feat, el, er, n);
    aggregate_kernel<4, 32, true><<<aggGrid, 256>>>(feat, el, er, b2, src, rp, h, n);

    // ---- layer 3: 1 head x 64; elr separate (head spans all col-warps)
    gemm_mma_kernel<128, 64, false><<<gemmGrid, 512>>>(h, W3, nullptr, nullptr, feat, el, er, n);
    elr_kernel<1, 64><<<elrGrid1, 256>>>(feat, al3, ar3, el, er, n);
    aggregate_kernel<1, 64, false><<<aggGrid, 256>>>(feat, el, er, b3, src, rp, out, n);
}

// round 12
// speedup vs baseline: 2.0441x; 1.0511x over previous
#include <cuda_runtime.h>
#include <cuda_fp16.h>
#include <cstdint>

#define N_NODES 50000
#define N_EDGES 800000

// ---------------- scratch (static device globals; no allocation) -------------
__device__ __half g_feat[N_NODES * 128];   // fp16 message table (gather side)
__device__ float  g_h[N_NODES * 128];      // fp32 activations between layers
__device__ float  g_el[N_NODES * 4];
__device__ float  g_er[N_NODES * 4];
__device__ int    g_rp[N_NODES + 1];

// ---------------- helpers ----------------------------------------------------
__device__ __forceinline__ uint32_t f2tf32(float f) {
    uint32_t r;
    asm("cvt.rna.tf32.f32 %0, %1;" : "=r"(r) : "f"(f));
    return r;
}
__device__ __forceinline__ void mma_tf32(float* d, const uint32_t* a, const uint32_t* b) {
    asm volatile(
        "mma.sync.aligned.m16n8k8.row.col.f32.tf32.tf32.f32 "
        "{%0,%1,%2,%3}, {%4,%5,%6,%7}, {%8,%9}, {%0,%1,%2,%3};"
        : "+f"(d[0]), "+f"(d[1]), "+f"(d[2]), "+f"(d[3])
        : "r"(a[0]), "r"(a[1]), "r"(a[2]), "r"(a[3]), "r"(b[0]), "r"(b[1]));
}

// ---------------- CSR row_ptr from sorted dst --------------------------------
__global__ void rowptr_kernel(const int* __restrict__ dst, int* __restrict__ rp,
                              int n, int e) {
    int i = blockIdx.x * blockDim.x + threadIdx.x;
    if (i > n) return;
    int lo = 0, hi = e;
    while (lo < hi) {
        int mid = (lo + hi) >> 1;
        if (dst[mid] < i) lo = mid + 1; else hi = mid;
    }
    rp[i] = lo;
}

// ---------------- tf32 mma.sync GEMM, fp16 C, optional fused el/er -----------
// C[M,NC] = A[M,K] @ W[K,NC] (C stored fp16); FUSE requires NC=128, H=4, D=32.
// 256 threads = 8 warps (4 row-warps x 2 col-warps), BM=128 (R6 measured shape).
template <int K, int NC, bool FUSE>
__global__ void __launch_bounds__(256)
gemm_mma_kernel(const float* __restrict__ A, const float* __restrict__ W,
                const float* __restrict__ al, const float* __restrict__ ar,
                __half* __restrict__ C, float* __restrict__ el, float* __restrict__ er,
                int M) {
    constexpr int BM = 128, KC = 32;
    constexpr int WCOLS = NC / 2;              // 64 or 32
    constexpr int RT = 2;
    constexpr int CT = WCOLS / 8;              // 8 or 4
    constexpr int APAD = KC + 4;
    constexpr int WPAD = NC + 4;

    __shared__ uint32_t As[BM][APAD];
    __shared__ uint32_t Ws[KC][WPAD];
    __shared__ float s_al[NC], s_ar[NC];

    const int tid = threadIdx.x;
    const int wid = tid >> 5, lane = tid & 31;
    const int g = lane >> 2, t = lane & 3;
    const int warpRow = wid >> 1, warpCol = wid & 1;
    const int rowBase = blockIdx.x * BM;

    if (FUSE) {
        if (tid < NC) s_al[tid] = al[tid];
        else if (tid < 2 * NC) s_ar[tid - NC] = ar[tid - NC];
    }

    float acc[RT][CT][4];
#pragma unroll
    for (int i = 0; i < RT; i++)
#pragma unroll
        for (int j = 0; j < CT; j++)
#pragma unroll
            for (int q = 0; q < 4; q++) acc[i][j][q] = 0.f;

    for (int k0 = 0; k0 < K; k0 += KC) {
        if (k0 > 0) __syncthreads();
        {
            constexpr int UNITS = BM * KC / 4;        // 1024
#pragma unroll
            for (int u = tid; u < UNITS; u += 256) {
                int row = u >> 3;
                int c = (u & 7) << 2;
                float4 v = make_float4(0.f, 0.f, 0.f, 0.f);
                int grow = rowBase + row;
                if (grow < M)
                    v = *reinterpret_cast<const float4*>(A + (size_t)grow * K + k0 + c);
                As[row][c + 0] = f2tf32(v.x); As[row][c + 1] = f2tf32(v.y);
                As[row][c + 2] = f2tf32(v.z); As[row][c + 3] = f2tf32(v.w);
            }
        }
        {
            constexpr int UNITS = KC * NC / 4;
#pragma unroll
            for (int u = tid; u < UNITS; u += 256) {
                int k = u / (NC / 4);
                int c = (u % (NC / 4)) << 2;
                float4 v = *reinterpret_cast<const float4*>(W + (size_t)(k0 + k) * NC + c);
                Ws[k][c + 0] = f2tf32(v.x); Ws[k][c + 1] = f2tf32(v.y);
                Ws[k][c + 2] = f2tf32(v.z); Ws[k][c + 3] = f2tf32(v.w);
            }
        }
        __syncthreads();

#pragma unroll
        for (int ks = 0; ks < KC / 8; ks++) {
            const int kk = ks * 8;
            uint32_t afr[RT][4];
#pragma unroll
            for (int rt = 0; rt < RT; rt++) {
                int r0 = warpRow * 32 + rt * 16 + g;
                afr[rt][0] = As[r0][kk + t];
                afr[rt][1] = As[r0 + 8][kk + t];
                afr[rt][2] = As[r0][kk + t + 4];
                afr[rt][3] = As[r0 + 8][kk + t + 4];
            }
            uint32_t bfr[CT][2];
#pragma unroll
            for (int ct = 0; ct < CT; ct++) {
                int n = warpCol * WCOLS + ct * 8 + g;
                bfr[ct][0] = Ws[kk + t][n];
                bfr[ct][1] = Ws[kk + t + 4][n];
            }
#pragma unroll
            for (int rt = 0; rt < RT; rt++)
#pragma unroll
                for (int ct = 0; ct < CT; ct++)
                    mma_tf32(acc[rt][ct], afr[rt], bfr[ct]);
        }
    }

    // ---- write C (fp16) + fused el/er ----
#pragma unroll
    for (int rt = 0; rt < RT; rt++) {
        int r0 = rowBase + warpRow * 32 + rt * 16 + g;
        int r1 = r0 + 8;
#pragma unroll
        for (int ct = 0; ct < CT; ct++) {
            int col = warpCol * WCOLS + ct * 8 + t * 2;   // even -> half2 4B-aligned
            if (r0 < M)
                *reinterpret_cast<__half2*>(C + (size_t)r0 * NC + col) =
                    __floats2half2_rn(acc[rt][ct][0], acc[rt][ct][1]);
            if (r1 < M)
                *reinterpret_cast<__half2*>(C + (size_t)r1 * NC + col) =
                    __floats2half2_rn(acc[rt][ct][2], acc[rt][ct][3]);
        }
        if (FUSE) {
            // NC=128, H=4, D=32: warp strip = heads {2*warpCol, 2*warpCol+1}
#pragma unroll
            for (int hh = 0; hh < 2; hh++) {
                float sl0 = 0.f, sr0 = 0.f, sl1 = 0.f, sr1 = 0.f;
#pragma unroll
                for (int ct = hh * (CT / 2); ct < (hh + 1) * (CT / 2); ct++) {
                    int col = warpCol * WCOLS + ct * 8 + t * 2;
#pragma unroll
                    for (int j = 0; j < 2; j++) {
                        float a_l = s_al[col + j], a_r = s_ar[col + j];
                        sl0 = fmaf(acc[rt][ct][j], a_l, sl0);
                        sr0 = fmaf(acc[rt][ct][j], a_r, sr0);
                        sl1 = fmaf(acc[rt][ct][2 + j], a_l, sl1);
                        sr1 = fmaf(acc[rt][ct][2 + j], a_r, sr1);
                    }
                }
#pragma unroll
                for (int d = 1; d < 4; d <<= 1) {
                    sl0 += __shfl_xor_sync(0xFFFFFFFF, sl0, d);
                    sr0 += __shfl_xor_sync(0xFFFFFFFF, sr0, d);
                    sl1 += __shfl_xor_sync(0xFFFFFFFF, sl1, d);
                    sr1 += __shfl_xor_sync(0xFFFFFFFF, sr1, d);
                }
                if (t == 0) {
                    int head = warpCol * 2 + hh;
                    if (r0 < M) { el[(size_t)r0 * 4 + head] = sl0; er[(size_t)r0 * 4 + head] = sr0; }
                    if (r1 < M) { el[(size_t)r1 * 4 + head] = sl1; er[(size_t)r1 * 4 + head] = sr1; }
                }
            }
        }
    }
}

// ---------------- layer-3 el/er from fp16 feat (H=1, D=64) ------------------
__global__ void elr64_kernel(const __half* __restrict__ feat,
                             const float* __restrict__ al, const float* __restrict__ ar,
                             float* __restrict__ el, float* __restrict__ er, int n) {
    int node = blockIdx.x * blockDim.x + threadIdx.x;
    if (node >= n) return;
    const uint4* p4 = reinterpret_cast<const uint4*>(feat + (size_t)node * 64);
    float sl = 0.f, sr = 0.f;
#pragma unroll
    for (int q = 0; q < 8; q++) {            // 8 x uint4 = 64 halves
        uint4 u = __ldg(&p4[q]);
        const uint32_t w[4] = {u.x, u.y, u.z, u.w};
#pragma unroll
        for (int j = 0; j < 4; j++) {
            float2 f = __half22float2(*reinterpret_cast<const __half2*>(&w[j]));
            int c = q * 8 + j * 2;
            sl = fmaf(f.x, al[c], fmaf(f.y, al[c + 1], sl));
            sr = fmaf(f.x, ar[c], fmaf(f.y, ar[c + 1], sr));
        }
    }
    el[node] = sl;
    er[node] = sr;
}

// ---------------- warp-per-dst-node softmax aggregation (no-max, fp16 gather)-
template <int H, int D, bool ELU>
__global__ void aggregate_kernel(const __half* __restrict__ feat,
                                 const float* __restrict__ el, const float* __restrict__ er,
                                 const float* __restrict__ bias,
                                 const int* __restrict__ src,
                                 const int* __restrict__ rp,
                                 float* __restrict__ out, int n) {
    constexpr int HD = H * D;
    constexpr int VPL = HD / 32;              // 4 (H=4) or 2 (H=1)
    int warp = (blockIdx.x * blockDim.x + threadIdx.x) >> 5;
    if (warp >= n) return;
    const int lane = threadIdx.x & 31;
    const int head = (lane * VPL) / D;

    const float erd = er[(size_t)warp * H + head];
    const int beg = rp[warp], end = rp[warp + 1];

    float s = 0.f;
    float acc[VPL];
#pragma unroll
    for (int j = 0; j < VPL; j++) acc[j] = 0.f;

    int i = beg;
    for (; i + 2 <= end; i += 2) {
        int sn0 = __ldg(&src[i]);
        int sn1 = __ldg(&src[i + 1]);
        float e0 = __ldg(&el[(size_t)sn0 * H + head]) + erd;
        float e1 = __ldg(&el[(size_t)sn1 * H + head]) + erd;
        e0 = e0 > 0.f ? e0 : 0.2f * e0;
        e1 = e1 > 0.f ? e1 : 0.2f * e1;
        float w0 = __expf(e0);
        float w1 = __expf(e1);
        if (VPL == 4) {
            uint2 u0 = __ldg(reinterpret_cast<const uint2*>(feat + (size_t)sn0 * HD) + lane);
            uint2 u1 = __ldg(reinterpret_cast<const uint2*>(feat + (size_t)sn1 * HD) + lane);
            float2 a0 = __half22float2(*reinterpret_cast<const __half2*>(&u0.x));
            float2 b0 = __half22float2(*reinterpret_cast<const __half2*>(&u0.y));
            float2 a1 = __half22float2(*reinterpret_cast<const __half2*>(&u1.x));
            float2 b1 = __half22float2(*reinterpret_cast<const __half2*>(&u1.y));
            acc[0] = fmaf(w0, a0.x, fmaf(w1, a1.x, acc[0]));
            acc[1] = fmaf(w0, a0.y, fmaf(w1, a1.y, acc[1]));
            acc[2] = fmaf(w0, b0.x, fmaf(w1, b1.x, acc[2]));
            acc[3] = fmaf(w0, b0.y, fmaf(w1, b1.y, acc[3]));
        } else {
            uint32_t u0 = __ldg(reinterpret_cast<const uint32_t*>(feat + (size_t)sn0 * HD) + lane);
            uint32_t u1 = __ldg(reinterpret_cast<const uint32_t*>(feat + (size_t)sn1 * HD) + lane);
            float2 a0 = __half22float2(*reinterpret_cast<const __half2*>(&u0));
            float2 a1 = __half22float2(*reinterpret_cast<const __half2*>(&u1));
            acc[0] = fmaf(w0, a0.x, fmaf(w1, a1.x, acc[0]));
            acc[1] = fmaf(w0, a0.y, fmaf(w1, a1.y, acc[1]));
        }
        s += w0 + w1;
    }
    if (i < end) {
        int sn = __ldg(&src[i]);
        float e = __ldg(&el[(size_t)sn * H + head]) + erd;
        e = e > 0.f ? e : 0.2f * e;
        float w = __expf(e);
        if (VPL == 4) {
            uint2 u = __ldg(reinterpret_cast<const uint2*>(feat + (size_t)sn * HD) + lane);
            float2 a = __half22float2(*reinterpret_cast<const __half2*>(&u.x));
            float2 b = __half22float2(*reinterpret_cast<const __half2*>(&u.y));
            acc[0] = fmaf(w, a.x, acc[0]);
            acc[1] = fmaf(w, a.y, acc[1]);
            acc[2] = fmaf(w, b.x, acc[2]);
            acc[3] = fmaf(w, b.y, acc[3]);
        } else {
            uint32_t u = __ldg(reinterpret_cast<const uint32_t*>(feat + (size_t)sn * HD) + lane);
            float2 a = __half22float2(*reinterpret_cast<const __half2*>(&u));
            acc[0] = fmaf(w, a.x, acc[0]);
            acc[1] = fmaf(w, a.y, acc[1]);
        }
        s += w;
    }

    float inv = 1.f / (s + 1e-9f);
#pragma unroll
    for (int j = 0; j < VPL; j++) {
        float v = acc[j] * inv + bias[lane * VPL + j];
        if (ELU) v = v > 0.f ? v : (__expf(v) - 1.f);
        acc[j] = v;
    }
    float* op = out + (size_t)warp * HD + lane * VPL;
    if (VPL == 4) *reinterpret_cast<float4*>(op) = make_float4(acc[0], acc[1], acc[2], acc[3]);
    else          *reinterpret_cast<float2*>(op) = make_float2(acc[0], acc[1]);
}

// ---------------- launcher ---------------------------------------------------
extern "C" void kernel_launch(void* const* d_in, const int* in_sizes, int n_in,
                              void* d_out, int out_size) {
    const float* x   = (const float*)d_in[0];
    const int* src   = (const int*)d_in[1];
    const int* dst   = (const int*)d_in[2];
    const float* W1  = (const float*)d_in[3];
    const float* al1 = (const float*)d_in[4];
    const float* ar1 = (const float*)d_in[5];
    const float* b1  = (const float*)d_in[6];
    const float* W2  = (const float*)d_in[7];
    const float* al2 = (const float*)d_in[8];
    const float* ar2 = (const float*)d_in[9];
    const float* b2  = (const float*)d_in[10];
    const float* W3  = (const float*)d_in[11];
    const float* al3 = (const float*)d_in[12];
    const float* ar3 = (const float*)d_in[13];
    const float* b3  = (const float*)d_in[14];
    float* out = (float*)d_out;

    const int n = N_NODES, e = N_EDGES;

    __half* feat;
    float *h, *el, *er;
    int *rp;
    cudaGetSymbolAddress((void**)&feat, g_feat);
    cudaGetSymbolAddress((void**)&h,    g_h);
    cudaGetSymbolAddress((void**)&el,   g_el);
    cudaGetSymbolAddress((void**)&er,   g_er);
    cudaGetSymbolAddress((void**)&rp,   g_rp);

    rowptr_kernel<<<(n + 1 + 255) / 256, 256>>>(dst, rp, n, e);

    const int gemmGrid = (n + 127) / 128;   // 391
    const int aggGrid = (n + 7) / 8;
    const int elrGrid1 = (n + 255) / 256;

    // ---- layer 1: x[50000,256] -> feat fp16, elr fused
    gemm_mma_kernel<256, 128, true><<<gemmGrid, 256>>>(x, W1, al1, ar1, feat, el, er, n);
    aggregate_kernel<4, 32, true><<<aggGrid, 256>>>(feat, el, er, b1, src, rp, h, n);

    // ---- layer 2
    gemm_mma_kernel<128, 128, true><<<gemmGrid, 256>>>(h, W2, al2, ar2, feat, el, er, n);
    aggregate_kernel<4, 32, true><<<aggGrid, 256>>>(feat, el, er, b2, src, rp, h, n);

    // ---- layer 3: 1 head x 64
    gemm_mma_kernel<128, 64, false><<<gemmGrid, 256>>>(h, W3, nullptr, nullptr, feat, el, er, n);
    elr64_kernel<<<elrGrid1, 256>>>(feat, al3, ar3, el, er, n);
    aggregate_kernel<1, 64, false><<<aggGrid, 256>>>(feat, el, er, b3, src, rp, out, n);
}

// round 13
// speedup vs baseline: 2.2705x; 1.1108x over previous
#include <cuda_runtime.h>
#include <cuda_fp16.h>
#include <cstdint>

#define N_NODES 50000
#define N_EDGES 800000

// ---------------- scratch (static device globals; no allocation) -------------
__device__ __half g_feat[N_NODES * 128];   // fp16 message table (gather side)
__device__ float  g_h[N_NODES * 128];      // fp32 activations between layers
__device__ float  g_el[N_NODES * 4];
__device__ float  g_er[N_NODES * 4];
__device__ int    g_rp[N_NODES + 1];

// ---------------- helpers ----------------------------------------------------
__device__ __forceinline__ void ldsm_x4(uint32_t* r, uint32_t a) {
    asm volatile("ldmatrix.sync.aligned.m8n8.x4.shared.b16 {%0,%1,%2,%3}, [%4];"
                 : "=r"(r[0]), "=r"(r[1]), "=r"(r[2]), "=r"(r[3]) : "r"(a));
}
__device__ __forceinline__ void ldsm_x4t(uint32_t* r, uint32_t a) {
    asm volatile("ldmatrix.sync.aligned.m8n8.x4.trans.shared.b16 {%0,%1,%2,%3}, [%4];"
                 : "=r"(r[0]), "=r"(r[1]), "=r"(r[2]), "=r"(r[3]) : "r"(a));
}
__device__ __forceinline__ void mma_f16(float* d, const uint32_t* a, const uint32_t* b) {
    asm volatile(
        "mma.sync.aligned.m16n8k16.row.col.f32.f16.f16.f32 "
        "{%0,%1,%2,%3}, {%4,%5,%6,%7}, {%8,%9}, {%0,%1,%2,%3};"
        : "+f"(d[0]), "+f"(d[1]), "+f"(d[2]), "+f"(d[3])
        : "r"(a[0]), "r"(a[1]), "r"(a[2]), "r"(a[3]), "r"(b[0]), "r"(b[1]));
}

// ---------------- CSR row_ptr from sorted dst --------------------------------
__global__ void rowptr_kernel(const int* __restrict__ dst, int* __restrict__ rp,
                              int n, int e) {
    int i = blockIdx.x * blockDim.x + threadIdx.x;
    if (i > n) return;
    int lo = 0, hi = e;
    while (lo < hi) {
        int mid = (lo + hi) >> 1;
        if (dst[mid] < i) lo = mid + 1; else hi = mid;
    }
    rp[i] = lo;
}

// ---------------- fp16 mma.sync GEMM (ldmatrix), fp16 C, optional fused elr --
// C[M,NC] = A[M,K] @ W[K,NC] (C fp16); FUSE requires NC=128, H=4, D=32.
// 256 threads = 8 warps (4 row-warps x 2 col-warps), BM=128.
template <int K, int NC, bool FUSE>
__global__ void __launch_bounds__(256)
gemm_mma_kernel(const float* __restrict__ A, const float* __restrict__ W,
                const float* __restrict__ al, const float* __restrict__ ar,
                __half* __restrict__ C, float* __restrict__ el, float* __restrict__ er,
                int M) {
    constexpr int BM = 128, KC = 32;
    constexpr int WCOLS = NC / 2;              // 64 or 32
    constexpr int RT = 2;
    constexpr int CT = WCOLS / 8;              // 8 or 4
    constexpr int APD = 56;                    // padded halves per A row (112B: banks 28i%32 distinct)
    constexpr int WPD = NC + 8;                // padded halves per W row (16B-aligned, conflict-free)

    __shared__ __align__(16) __half As[BM][APD];
    __shared__ __align__(16) __half Ws[KC][WPD];
    __shared__ float s_al[NC], s_ar[NC];

    const int tid = threadIdx.x;
    const int wid = tid >> 5, lane = tid & 31;
    const int g = lane >> 2, t = lane & 3;
    const int warpRow = wid >> 1, warpCol = wid & 1;
    const int rowBase = blockIdx.x * BM;
    const int lane16 = lane & 15, laneHi = (lane >> 4) << 3;

    if (FUSE) {
        if (tid < NC) s_al[tid] = al[tid];
        else if (tid < 2 * NC) s_ar[tid - NC] = ar[tid - NC];
    }

    float acc[RT][CT][4];
#pragma unroll
    for (int i = 0; i < RT; i++)
#pragma unroll
        for (int j = 0; j < CT; j++)
#pragma unroll
            for (int q = 0; q < 4; q++) acc[i][j][q] = 0.f;

    const uint32_t asb = (uint32_t)__cvta_generic_to_shared(&As[0][0]);
    const uint32_t wsb = (uint32_t)__cvta_generic_to_shared(&Ws[0][0]);

    for (int k0 = 0; k0 < K; k0 += KC) {
        if (k0 > 0) __syncthreads();
        // ---- load A chunk (BM x KC) -> fp16 SMEM ----
        {
            constexpr int UNITS = BM * KC / 4;        // 1024
#pragma unroll
            for (int u = tid; u < UNITS; u += 256) {
                int row = u >> 3;
                int c = (u & 7) << 2;
                float4 v = make_float4(0.f, 0.f, 0.f, 0.f);
                int grow = rowBase + row;
                if (grow < M)
                    v = *reinterpret_cast<const float4*>(A + (size_t)grow * K + k0 + c);
                *reinterpret_cast<__half2*>(&As[row][c])     = __floats2half2_rn(v.x, v.y);
                *reinterpret_cast<__half2*>(&As[row][c + 2]) = __floats2half2_rn(v.z, v.w);
            }
        }
        // ---- load W chunk (KC x NC) -> fp16 SMEM ----
        {
            constexpr int UNITS = KC * NC / 4;        // 1024 or 512
#pragma unroll
            for (int u = tid; u < UNITS; u += 256) {
                int k = u / (NC / 4);
                int c = (u % (NC / 4)) << 2;
                float4 v = *reinterpret_cast<const float4*>(W + (size_t)(k0 + k) * NC + c);
                *reinterpret_cast<__half2*>(&Ws[k][c])     = __floats2half2_rn(v.x, v.y);
                *reinterpret_cast<__half2*>(&Ws[k][c + 2]) = __floats2half2_rn(v.z, v.w);
            }
        }
        __syncthreads();

#pragma unroll
        for (int ks = 0; ks < 2; ks++) {              // 2 x k16 per KC=32 chunk
            const int kk = ks * 16;
            uint32_t afr[RT][4];
#pragma unroll
            for (int rt = 0; rt < RT; rt++) {
                int row = warpRow * 32 + rt * 16 + lane16;
                ldsm_x4(afr[rt], asb + (uint32_t)(row * APD + kk + laneHi) * 2u);
            }
            uint32_t bfr[CT / 2][4];
#pragma unroll
            for (int c2 = 0; c2 < CT / 2; c2++) {
                int n0 = warpCol * WCOLS + c2 * 16 + laneHi;
                ldsm_x4t(bfr[c2], wsb + (uint32_t)((kk + lane16) * WPD + n0) * 2u);
            }
#pragma unroll
            for (int rt = 0; rt < RT; rt++)
#pragma unroll
                for (int ct = 0; ct < CT; ct++)
                    mma_f16(acc[rt][ct], afr[rt], &bfr[ct >> 1][(ct & 1) * 2]);
        }
    }

    // ---- write C (fp16) + fused el/er ----
#pragma unroll
    for (int rt = 0; rt < RT; rt++) {
        int r0 = rowBase + warpRow * 32 + rt * 16 + g;
        int r1 = r0 + 8;
#pragma unroll
        for (int ct = 0; ct < CT; ct++) {
            int col = warpCol * WCOLS + ct * 8 + t * 2;
            if (r0 < M)
                *reinterpret_cast<__half2*>(C + (size_t)r0 * NC + col) =
                    __floats2half2_rn(acc[rt][ct][0], acc[rt][ct][1]);
            if (r1 < M)
                *reinterpret_cast<__half2*>(C + (size_t)r1 * NC + col) =
                    __floats2half2_rn(acc[rt][ct][2], acc[rt][ct][3]);
        }
        if (FUSE) {
            // NC=128, H=4, D=32: warp strip = heads {2*warpCol, 2*warpCol+1}
#pragma unroll
            for (int hh = 0; hh < 2; hh++) {
                float sl0 = 0.f, sr0 = 0.f, sl1 = 0.f, sr1 = 0.f;
#pragma unroll
                for (int ct = hh * (CT / 2); ct < (hh + 1) * (CT / 2); ct++) {
                    int col = warpCol * WCOLS + ct * 8 + t * 2;
#pragma unroll
                    for (int j = 0; j < 2; j++) {
                        float a_l = s_al[col + j], a_r = s_ar[col + j];
                        sl0 = fmaf(acc[rt][ct][j], a_l, sl0);
                        sr0 = fmaf(acc[rt][ct][j], a_r, sr0);
                        sl1 = fmaf(acc[rt][ct][2 + j], a_l, sl1);
                        sr1 = fmaf(acc[rt][ct][2 + j], a_r, sr1);
                    }
                }
#pragma unroll
                for (int d = 1; d < 4; d <<= 1) {
                    sl0 += __shfl_xor_sync(0xFFFFFFFF, sl0, d);
                    sr0 += __shfl_xor_sync(0xFFFFFFFF, sr0, d);
                    sl1 += __shfl_xor_sync(0xFFFFFFFF, sl1, d);
                    sr1 += __shfl_xor_sync(0xFFFFFFFF, sr1, d);
                }
                if (t == 0) {
                    int head = warpCol * 2 + hh;
                    if (r0 < M) { el[(size_t)r0 * 4 + head] = sl0; er[(size_t)r0 * 4 + head] = sr0; }
                    if (r1 < M) { el[(size_t)r1 * 4 + head] = sl1; er[(size_t)r1 * 4 + head] = sr1; }
                }
            }
        }
    }
}

// ---------------- layer-3 el/er from fp16 feat (H=1, D=64) ------------------
__global__ void elr64_kernel(const __half* __restrict__ feat,
                             const float* __restrict__ al, const float* __restrict__ ar,
                             float* __restrict__ el, float* __restrict__ er, int n) {
    int node = blockIdx.x * blockDim.x + threadIdx.x;
    if (node >= n) return;
    const uint4* p4 = reinterpret_cast<const uint4*>(feat + (size_t)node * 64);
    float sl = 0.f, sr = 0.f;
#pragma unroll
    for (int q = 0; q < 8; q++) {            // 8 x uint4 = 64 halves
        uint4 u = __ldg(&p4[q]);
        const uint32_t w[4] = {u.x, u.y, u.z, u.w};
#pragma unroll
        for (int j = 0; j < 4; j++) {
            float2 f = __half22float2(*reinterpret_cast<const __half2*>(&w[j]));
            int c = q * 8 + j * 2;
            sl = fmaf(f.x, al[c], fmaf(f.y, al[c + 1], sl));
            sr = fmaf(f.x, ar[c], fmaf(f.y, ar[c + 1], sr));
        }
    }
    el[node] = sl;
    er[node] = sr;
}

// ---------------- warp-per-dst-node softmax aggregation (no-max, fp16 gather)-
template <int H, int D, bool ELU>
__global__ void aggregate_kernel(const __half* __restrict__ feat,
                                 const float* __restrict__ el, const float* __restrict__ er,
                                 const float* __restrict__ bias,
                                 const int* __restrict__ src,
                                 const int* __restrict__ rp,
                                 float* __restrict__ out, int n) {
    constexpr int HD = H * D;
    constexpr int VPL = HD / 32;              // 4 (H=4) or 2 (H=1)
    int warp = (blockIdx.x * blockDim.x + threadIdx.x) >> 5;
    if (warp >= n) return;
    const int lane = threadIdx.x & 31;
    const int head = (lane * VPL) / D;

    const float erd = er[(size_t)warp * H + head];
    const int beg = rp[warp], end = rp[warp + 1];

    float s = 0.f;
    float acc[VPL];
#pragma unroll
    for (int j = 0; j < VPL; j++) acc[j] = 0.f;

    int i = beg;
    for (; i + 2 <= end; i += 2) {
        int sn0 = __ldg(&src[i]);
        int sn1 = __ldg(&src[i + 1]);
        float e0 = __ldg(&el[(size_t)sn0 * H + head]) + erd;
        float e1 = __ldg(&el[(size_t)sn1 * H + head]) + erd;
        e0 = e0 > 0.f ? e0 : 0.2f * e0;
        e1 = e1 > 0.f ? e1 : 0.2f * e1;
        float w0 = __expf(e0);
        float w1 = __expf(e1);
        if (VPL == 4) {
            uint2 u0 = __ldg(reinterpret_cast<const uint2*>(feat + (size_t)sn0 * HD) + lane);
            uint2 u1 = __ldg(reinterpret_cast<const uint2*>(feat + (size_t)sn1 * HD) + lane);
            float2 a0 = __half22float2(*reinterpret_cast<const __half2*>(&u0.x));
            float2 b0 = __half22float2(*reinterpret_cast<const __half2*>(&u0.y));
            float2 a1 = __half22float2(*reinterpret_cast<const __half2*>(&u1.x));
            float2 b1 = __half22float2(*reinterpret_cast<const __half2*>(&u1.y));
            acc[0] = fmaf(w0, a0.x, fmaf(w1, a1.x, acc[0]));
            acc[1] = fmaf(w0, a0.y, fmaf(w1, a1.y, acc[1]));
            acc[2] = fmaf(w0, b0.x, fmaf(w1, b1.x, acc[2]));
            acc[3] = fmaf(w0, b0.y, fmaf(w1, b1.y, acc[3]));
        } else {
            uint32_t u0 = __ldg(reinterpret_cast<const uint32_t*>(feat + (size_t)sn0 * HD) + lane);
            uint32_t u1 = __ldg(reinterpret_cast<const uint32_t*>(feat + (size_t)sn1 * HD) + lane);
            float2 a0 = __half22float2(*reinterpret_cast<const __half2*>(&u0));
            float2 a1 = __half22float2(*reinterpret_cast<const __half2*>(&u1));
            acc[0] = fmaf(w0, a0.x, fmaf(w1, a1.x, acc[0]));
            acc[1] = fmaf(w0, a0.y, fmaf(w1, a1.y, acc[1]));
        }
        s += w0 + w1;
    }
    if (i < end) {
        int sn = __ldg(&src[i]);
        float e = __ldg(&el[(size_t)sn * H + head]) + erd;
        e = e > 0.f ? e : 0.2f * e;
        float w = __expf(e);
        if (VPL == 4) {
            uint2 u = __ldg(reinterpret_cast<const uint2*>(feat + (size_t)sn * HD) + lane);
            float2 a = __half22float2(*reinterpret_cast<const __half2*>(&u.x));
            float2 b = __half22float2(*reinterpret_cast<const __half2*>(&u.y));
            acc[0] = fmaf(w, a.x, acc[0]);
            acc[1] = fmaf(w, a.y, acc[1]);
            acc[2] = fmaf(w, b.x, acc[2]);
            acc[3] = fmaf(w, b.y, acc[3]);
        } else {
            uint32_t u = __ldg(reinterpret_cast<const uint32_t*>(feat + (size_t)sn * HD) + lane);
            float2 a = __half22float2(*reinterpret_cast<const __half2*>(&u));
            acc[0] = fmaf(w, a.x, acc[0]);
            acc[1] = fmaf(w, a.y, acc[1]);
        }
        s += w;
    }

    float inv = 1.f / (s + 1e-9f);
#pragma unroll
    for (int j = 0; j < VPL; j++) {
        float v = acc[j] * inv + bias[lane * VPL + j];
        if (ELU) v = v > 0.f ? v : (__expf(v) - 1.f);
        acc[j] = v;
    }
    float* op = out + (size_t)warp * HD + lane * VPL;
    if (VPL == 4) *reinterpret_cast<float4*>(op) = make_float4(acc[0], acc[1], acc[2], acc[3]);
    else          *reinterpret_cast<float2*>(op) = make_float2(acc[0], acc[1]);
}

// ---------------- launcher ---------------------------------------------------
extern "C" void kernel_launch(void* const* d_in, const int* in_sizes, int n_in,
                              void* d_out, int out_size) {
    const float* x   = (const float*)d_in[0];
    const int* src   = (const int*)d_in[1];
    const int* dst   = (const int*)d_in[2];
    const float* W1  = (const float*)d_in[3];
    const float* al1 = (const float*)d_in[4];
    const float* ar1 = (const float*)d_in[5];
    const float* b1  = (const float*)d_in[6];
    const float* W2  = (const float*)d_in[7];
    const float* al2 = (const float*)d_in[8];
    const float* ar2 = (const float*)d_in[9];
    const float* b2  = (const float*)d_in[10];
    const float* W3  = (const float*)d_in[11];
    const float* al3 = (const float*)d_in[12];
    const float* ar3 = (const float*)d_in[13];
    const float* b3  = (const float*)d_in[14];
    float* out = (float*)d_out;

    const int n = N_NODES, e = N_EDGES;

    __half* feat;
    float *h, *el, *er;
    int *rp;
    cudaGetSymbolAddress((void**)&feat, g_feat);
    cudaGetSymbolAddress((void**)&h,    g_h);
    cudaGetSymbolAddress((void**)&el,   g_el);
    cudaGetSymbolAddress((void**)&er,   g_er);
    cudaGetSymbolAddress((void**)&rp,   g_rp);

    rowptr_kernel<<<(n + 1 + 255) / 256, 256>>>(dst, rp, n, e);

    const int gemmGrid = (n + 127) / 128;   // 391
    const int aggGrid = (n + 7) / 8;
    const int elrGrid1 = (n + 255) / 256;

    // ---- layer 1: x[50000,256] -> feat fp16, elr fused
    gemm_mma_kernel<256, 128, true><<<gemmGrid, 256>>>(x, W1, al1, ar1, feat, el, er, n);
    aggregate_kernel<4, 32, true><<<aggGrid, 256>>>(feat, el, er, b1, src, rp, h, n);

    // ---- layer 2
    gemm_mma_kernel<128, 128, true><<<gemmGrid, 256>>>(h, W2, al2, ar2, feat, el, er, n);
    aggregate_kernel<4, 32, true><<<aggGrid, 256>>>(feat, el, er, b2, src, rp, h, n);

    // ---- layer 3: 1 head x 64
    gemm_mma_kernel<128, 64, false><<<gemmGrid, 256>>>(h, W3, nullptr, nullptr, feat, el, er, n);
    elr64_kernel<<<elrGrid1, 256>>>(feat, al3, ar3, el, er, n);
    aggregate_kernel<1, 64, false><<<aggGrid, 256>>>(feat, el, er, b3, src, rp, out, n);
}

// round 14
// speedup vs baseline: 2.5046x; 1.1031x over previous
#include <cuda_runtime.h>
#include <cuda_fp16.h>
#include <cstdint>

#define N_NODES 50000
#define N_EDGES 800000

// ---------------- scratch (static device globals; no allocation) -------------
__device__ __half g_feat[N_NODES * 128];   // fp16 message table (gather side)
__device__ __half g_h[N_NODES * 128];      // fp16 activations between layers
__device__ float  g_el[N_NODES * 4];
__device__ float  g_er[N_NODES * 4];
__device__ int    g_rp[N_NODES + 1];

// ---------------- helpers ----------------------------------------------------
__device__ __forceinline__ void ldsm_x4(uint32_t* r, uint32_t a) {
    asm volatile("ldmatrix.sync.aligned.m8n8.x4.shared.b16 {%0,%1,%2,%3}, [%4];"
                 : "=r"(r[0]), "=r"(r[1]), "=r"(r[2]), "=r"(r[3]) : "r"(a));
}
__device__ __forceinline__ void ldsm_x4t(uint32_t* r, uint32_t a) {
    asm volatile("ldmatrix.sync.aligned.m8n8.x4.trans.shared.b16 {%0,%1,%2,%3}, [%4];"
                 : "=r"(r[0]), "=r"(r[1]), "=r"(r[2]), "=r"(r[3]) : "r"(a));
}
__device__ __forceinline__ void mma_f16(float* d, const uint32_t* a, const uint32_t* b) {
    asm volatile(
        "mma.sync.aligned.m16n8k16.row.col.f32.f16.f16.f32 "
        "{%0,%1,%2,%3}, {%4,%5,%6,%7}, {%8,%9}, {%0,%1,%2,%3};"
        : "+f"(d[0]), "+f"(d[1]), "+f"(d[2]), "+f"(d[3])
        : "r"(a[0]), "r"(a[1]), "r"(a[2]), "r"(a[3]), "r"(b[0]), "r"(b[1]));
}

// ---------------- CSR row_ptr from sorted dst --------------------------------
__global__ void rowptr_kernel(const int* __restrict__ dst, int* __restrict__ rp,
                              int n, int e) {
    int i = blockIdx.x * blockDim.x + threadIdx.x;
    if (i > n) return;
    int lo = 0, hi = e;
    while (lo < hi) {
        int mid = (lo + hi) >> 1;
        if (dst[mid] < i) lo = mid + 1; else hi = mid;
    }
    rp[i] = lo;
}

// ---------------- fp16 mma.sync GEMM, KC=128 chunks, dynamic SMEM ------------
// C[M,NC] = A[M,K] @ W[K,NC] (C fp16); FUSE requires NC=128, H=4, D=32.
// A may be fp32 (layer 1) or fp16 (layers 2-3).
// 256 threads = 8 warps (4 row-warps x 2 col-warps), BM=128.
template <int K, int NC, bool FUSE, typename AT>
__global__ void __launch_bounds__(256)
gemm_mma_kernel(const AT* __restrict__ A, const float* __restrict__ W,
                const float* __restrict__ al, const float* __restrict__ ar,
                __half* __restrict__ C, float* __restrict__ el, float* __restrict__ er,
                int M) {
    constexpr int BM = 128, KC = 128;
    constexpr int NCHUNK = K / KC;             // 2 (K=256) or 1
    constexpr int WCOLS = NC / 2;              // 64 or 32
    constexpr int RT = 2;
    constexpr int CT = WCOLS / 8;              // 8 or 4
    constexpr int APD = KC + 8;                // 136 halves / A row
    constexpr int WPD = NC + 8;                // 136 or 72 halves / W row
    constexpr bool A32 = (sizeof(AT) == 4);

    extern __shared__ __half dynsmem[];
    __half (*As)[APD] = reinterpret_cast<__half(*)[APD]>(dynsmem);
    __half (*Ws)[WPD] = reinterpret_cast<__half(*)[WPD]>(dynsmem + BM * APD);
    __shared__ float s_al[NC], s_ar[NC];

    const int tid = threadIdx.x;
    const int wid = tid >> 5, lane = tid & 31;
    const int g = lane >> 2, t = lane & 3;
    const int warpRow = wid >> 1, warpCol = wid & 1;
    const int rowBase = blockIdx.x * BM;
    const int lane16 = lane & 15, laneHi = (lane >> 4) << 3;

    if (FUSE) {
        if (tid < NC) s_al[tid] = al[tid];
        else if (tid < 2 * NC) s_ar[tid - NC] = ar[tid - NC];
    }

    float acc[RT][CT][4];
#pragma unroll
    for (int i = 0; i < RT; i++)
#pragma unroll
        for (int j = 0; j < CT; j++)
#pragma unroll
            for (int q = 0; q < 4; q++) acc[i][j][q] = 0.f;

    const uint32_t asb = (uint32_t)__cvta_generic_to_shared(&As[0][0]);
    const uint32_t wsb = (uint32_t)__cvta_generic_to_shared(&Ws[0][0]);

    for (int ch = 0; ch < NCHUNK; ch++) {
        const int k0 = ch * KC;
        if (ch > 0) __syncthreads();
        // ---- load A chunk (BM x KC) -> fp16 SMEM ----
        if (A32) {
            constexpr int UNITS = BM * KC / 4;        // 4096
#pragma unroll
            for (int u = tid; u < UNITS; u += 256) {
                int row = u >> 5;                     // /(KC/4)=32
                int c = (u & 31) << 2;
                float4 v = make_float4(0.f, 0.f, 0.f, 0.f);
                int grow = rowBase + row;
                if (grow < M)
                    v = *reinterpret_cast<const float4*>(
                        reinterpret_cast<const float*>(A) + (size_t)grow * K + k0 + c);
                *reinterpret_cast<__half2*>(&As[row][c])     = __floats2half2_rn(v.x, v.y);
                *reinterpret_cast<__half2*>(&As[row][c + 2]) = __floats2half2_rn(v.z, v.w);
            }
        } else {
            constexpr int UNITS = BM * KC / 8;        // 2048
#pragma unroll
            for (int u = tid; u < UNITS; u += 256) {
                int row = u >> 4;                     // /(KC/8)=16
                int c = (u & 15) << 3;
                uint4 v = make_uint4(0u, 0u, 0u, 0u);
                int grow = rowBase + row;
                if (grow < M)
                    v = *reinterpret_cast<const uint4*>(
                        reinterpret_cast<const __half*>(A) + (size_t)grow * K + k0 + c);
                *reinterpret_cast<uint4*>(&As[row][c]) = v;
            }
        }
        // ---- load W chunk (KC x NC) -> fp16 SMEM ----
        {
            constexpr int UNITS = KC * NC / 4;        // 4096 or 2048
#pragma unroll
            for (int u = tid; u < UNITS; u += 256) {
                int k = u / (NC / 4);
                int c = (u % (NC / 4)) << 2;
                float4 v = *reinterpret_cast<const float4*>(W + (size_t)(k0 + k) * NC + c);
                *reinterpret_cast<__half2*>(&Ws[k][c])     = __floats2half2_rn(v.x, v.y);
                *reinterpret_cast<__half2*>(&Ws[k][c + 2]) = __floats2half2_rn(v.z, v.w);
            }
        }
        __syncthreads();

#pragma unroll
        for (int ks = 0; ks < KC / 16; ks++) {
            const int kk = ks * 16;
            uint32_t afr[RT][4];
#pragma unroll
            for (int rt = 0; rt < RT; rt++) {
                int row = warpRow * 32 + rt * 16 + lane16;
                ldsm_x4(afr[rt], asb + (uint32_t)(row * APD + kk + laneHi) * 2u);
            }
            uint32_t bfr[CT / 2][4];
#pragma unroll
            for (int c2 = 0; c2 < CT / 2; c2++) {
                int n0 = warpCol * WCOLS + c2 * 16 + laneHi;
                ldsm_x4t(bfr[c2], wsb + (uint32_t)((kk + lane16) * WPD + n0) * 2u);
            }
#pragma unroll
            for (int rt = 0; rt < RT; rt++)
#pragma unroll
                for (int ct = 0; ct < CT; ct++)
                    mma_f16(acc[rt][ct], afr[rt], &bfr[ct >> 1][(ct & 1) * 2]);
        }
    }

    // ---- write C (fp16) + fused el/er ----
#pragma unroll
    for (int rt = 0; rt < RT; rt++) {
        int r0 = rowBase + warpRow * 32 + rt * 16 + g;
        int r1 = r0 + 8;
#pragma unroll
        for (int ct = 0; ct < CT; ct++) {
            int col = warpCol * WCOLS + ct * 8 + t * 2;
            if (r0 < M)
                *reinterpret_cast<__half2*>(C + (size_t)r0 * NC + col) =
                    __floats2half2_rn(acc[rt][ct][0], acc[rt][ct][1]);
            if (r1 < M)
                *reinterpret_cast<__half2*>(C + (size_t)r1 * NC + col) =
                    __floats2half2_rn(acc[rt][ct][2], acc[rt][ct][3]);
        }
        if (FUSE) {
            // NC=128, H=4, D=32: warp strip = heads {2*warpCol, 2*warpCol+1}
#pragma unroll
            for (int hh = 0; hh < 2; hh++) {
                float sl0 = 0.f, sr0 = 0.f, sl1 = 0.f, sr1 = 0.f;
#pragma unroll
                for (int ct = hh * (CT / 2); ct < (hh + 1) * (CT / 2); ct++) {
                    int col = warpCol * WCOLS + ct * 8 + t * 2;
#pragma unroll
                    for (int j = 0; j < 2; j++) {
                        float a_l = s_al[col + j], a_r = s_ar[col + j];
                        sl0 = fmaf(acc[rt][ct][j], a_l, sl0);
                        sr0 = fmaf(acc[rt][ct][j], a_r, sr0);
                        sl1 = fmaf(acc[rt][ct][2 + j], a_l, sl1);
                        sr1 = fmaf(acc[rt][ct][2 + j], a_r, sr1);
                    }
                }
#pragma unroll
                for (int d = 1; d < 4; d <<= 1) {
                    sl0 += __shfl_xor_sync(0xFFFFFFFF, sl0, d);
                    sr0 += __shfl_xor_sync(0xFFFFFFFF, sr0, d);
                    sl1 += __shfl_xor_sync(0xFFFFFFFF, sl1, d);
                    sr1 += __shfl_xor_sync(0xFFFFFFFF, sr1, d);
                }
                if (t == 0) {
                    int head = warpCol * 2 + hh;
                    if (r0 < M) { el[(size_t)r0 * 4 + head] = sl0; er[(size_t)r0 * 4 + head] = sr0; }
                    if (r1 < M) { el[(size_t)r1 * 4 + head] = sl1; er[(size_t)r1 * 4 + head] = sr1; }
                }
            }
        }
    }
}

// ---------------- layer-3 el/er from fp16 feat (H=1, D=64) ------------------
__global__ void elr64_kernel(const __half* __restrict__ feat,
                             const float* __restrict__ al, const float* __restrict__ ar,
                             float* __restrict__ el, float* __restrict__ er, int n) {
    int node = blockIdx.x * blockDim.x + threadIdx.x;
    if (node >= n) return;
    const uint4* p4 = reinterpret_cast<const uint4*>(feat + (size_t)node * 64);
    float sl = 0.f, sr = 0.f;
#pragma unroll
    for (int q = 0; q < 8; q++) {
        uint4 u = __ldg(&p4[q]);
        const uint32_t w[4] = {u.x, u.y, u.z, u.w};
#pragma unroll
        for (int j = 0; j < 4; j++) {
            float2 f = __half22float2(*reinterpret_cast<const __half2*>(&w[j]));
            int c = q * 8 + j * 2;
            sl = fmaf(f.x, al[c], fmaf(f.y, al[c + 1], sl));
            sr = fmaf(f.x, ar[c], fmaf(f.y, ar[c + 1], sr));
        }
    }
    el[node] = sl;
    er[node] = sr;
}

// ---------------- warp-per-dst-node softmax aggregation (no-max, unroll-4) ---
// OutT = __half (intermediate h) or float (final logits).
template <int H, int D, bool ELU, typename OutT>
__global__ void aggregate_kernel(const __half* __restrict__ feat,
                                 const float* __restrict__ el, const float* __restrict__ er,
                                 const float* __restrict__ bias,
                                 const int* __restrict__ src,
                                 const int* __restrict__ rp,
                                 OutT* __restrict__ out, int n) {
    constexpr int HD = H * D;
    constexpr int VPL = HD / 32;              // 4 (H=4) or 2 (H=1)
    int warp = (blockIdx.x * blockDim.x + threadIdx.x) >> 5;
    if (warp >= n) return;
    const int lane = threadIdx.x & 31;
    const int head = (lane * VPL) / D;

    const float erd = er[(size_t)warp * H + head];
    const int beg = rp[warp], end = rp[warp + 1];

    float s = 0.f;
    float acc[VPL];
#pragma unroll
    for (int j = 0; j < VPL; j++) acc[j] = 0.f;

    int i = beg;
    for (; i + 4 <= end; i += 4) {
        int sn[4];
        float w[4];
#pragma unroll
        for (int j = 0; j < 4; j++) sn[j] = __ldg(&src[i + j]);
#pragma unroll
        for (int j = 0; j < 4; j++) {
            float e = __ldg(&el[(size_t)sn[j] * H + head]) + erd;
            e = e > 0.f ? e : 0.2f * e;
            w[j] = __expf(e);
        }
        if (VPL == 4) {
            uint2 u[4];
#pragma unroll
            for (int j = 0; j < 4; j++)
                u[j] = __ldg(reinterpret_cast<const uint2*>(feat + (size_t)sn[j] * HD) + lane);
#pragma unroll
            for (int j = 0; j < 4; j++) {
                float2 a = __half22float2(*reinterpret_cast<const __half2*>(&u[j].x));
                float2 b = __half22float2(*reinterpret_cast<const __half2*>(&u[j].y));
                acc[0] = fmaf(w[j], a.x, acc[0]);
                acc[1] = fmaf(w[j], a.y, acc[1]);
                acc[2] = fmaf(w[j], b.x, acc[2]);
                acc[3] = fmaf(w[j], b.y, acc[3]);
            }
        } else {
            uint32_t u[4];
#pragma unroll
            for (int j = 0; j < 4; j++)
                u[j] = __ldg(reinterpret_cast<const uint32_t*>(feat + (size_t)sn[j] * HD) + lane);
#pragma unroll
            for (int j = 0; j < 4; j++) {
                float2 a = __half22float2(*reinterpret_cast<const __half2*>(&u[j]));
                acc[0] = fmaf(w[j], a.x, acc[0]);
                acc[1] = fmaf(w[j], a.y, acc[1]);
            }
        }
        s += (w[0] + w[1]) + (w[2] + w[3]);
    }
    for (; i < end; i++) {
        int sn = __ldg(&src[i]);
        float e = __ldg(&el[(size_t)sn * H + head]) + erd;
        e = e > 0.f ? e : 0.2f * e;
        float w = __expf(e);
        if (VPL == 4) {
            uint2 u = __ldg(reinterpret_cast<const uint2*>(feat + (size_t)sn * HD) + lane);
            float2 a = __half22float2(*reinterpret_cast<const __half2*>(&u.x));
            float2 b = __half22float2(*reinterpret_cast<const __half2*>(&u.y));
            acc[0] = fmaf(w, a.x, acc[0]);
            acc[1] = fmaf(w, a.y, acc[1]);
            acc[2] = fmaf(w, b.x, acc[2]);
            acc[3] = fmaf(w, b.y, acc[3]);
        } else {
            uint32_t u = __ldg(reinterpret_cast<const uint32_t*>(feat + (size_t)sn * HD) + lane);
            float2 a = __half22float2(*reinterpret_cast<const __half2*>(&u));
            acc[0] = fmaf(w, a.x, acc[0]);
            acc[1] = fmaf(w, a.y, acc[1]);
        }
        s += w;
    }

    float inv = 1.f / (s + 1e-9f);
#pragma unroll
    for (int j = 0; j < VPL; j++) {
        float v = acc[j] * inv + bias[lane * VPL + j];
        if (ELU) v = v > 0.f ? v : (__expf(v) - 1.f);
        acc[j] = v;
    }
    if (sizeof(OutT) == 2) {     // fp16 h output
        __half2 h0 = __floats2half2_rn(acc[0], acc[1]);
        uint2 val;
        val.x = *reinterpret_cast<uint32_t*>(&h0);
        if (VPL == 4) {
            __half2 h1 = __floats2half2_rn(acc[2], acc[3]);
            val.y = *reinterpret_cast<uint32_t*>(&h1);
            *reinterpret_cast<uint2*>(reinterpret_cast<__half*>(out) + (size_t)warp * HD + lane * VPL) = val;
        } else {
            *reinterpret_cast<uint32_t*>(reinterpret_cast<__half*>(out) + (size_t)warp * HD + lane * VPL) = val.x;
        }
    } else {                     // fp32 final output
        float* op = reinterpret_cast<float*>(out) + (size_t)warp * HD + lane * VPL;
        if (VPL == 4) *reinterpret_cast<float4*>(op) = make_float4(acc[0], acc[1], acc[2], acc[3]);
        else          *reinterpret_cast<float2*>(op) = make_float2(acc[0], acc[1]);
    }
}

// ---------------- launcher ---------------------------------------------------
extern "C" void kernel_launch(void* const* d_in, const int* in_sizes, int n_in,
                              void* d_out, int out_size) {
    const float* x   = (const float*)d_in[0];
    const int* src   = (const int*)d_in[1];
    const int* dst   = (const int*)d_in[2];
    const float* W1  = (const float*)d_in[3];
    const float* al1 = (const float*)d_in[4];
    const float* ar1 = (const float*)d_in[5];
    const float* b1  = (const float*)d_in[6];
    const float* W2  = (const float*)d_in[7];
    const float* al2 = (const float*)d_in[8];
    const float* ar2 = (const float*)d_in[9];
    const float* b2  = (const float*)d_in[10];
    const float* W3  = (const float*)d_in[11];
    const float* al3 = (const float*)d_in[12];
    const float* ar3 = (const float*)d_in[13];
    const float* b3  = (const float*)d_in[14];
    float* out = (float*)d_out;

    const int n = N_NODES, e = N_EDGES;

    __half *feat, *h;
    float *el, *er;
    int *rp;
    cudaGetSymbolAddress((void**)&feat, g_feat);
    cudaGetSymbolAddress((void**)&h,    g_h);
    cudaGetSymbolAddress((void**)&el,   g_el);
    cudaGetSymbolAddress((void**)&er,   g_er);
    cudaGetSymbolAddress((void**)&rp,   g_rp);

    rowptr_kernel<<<(n + 1 + 255) / 256, 256>>>(dst, rp, n, e);

    const int gemmGrid = (n + 127) / 128;   // 391
    const int aggGrid = (n + 7) / 8;
    const int elrGrid1 = (n + 255) / 256;

    // dynamic SMEM: As[128][136] + Ws[128][NC+8] halves
    const int smemA = 128 * 136 * 2;                       // 34816
    const int smem128 = smemA + 128 * 136 * 2;             // 69632
    const int smem64  = smemA + 128 * 72 * 2;              // 53248

    cudaFuncSetAttribute(gemm_mma_kernel<256, 128, true, float>,
                         cudaFuncAttributeMaxDynamicSharedMemorySize, smem128);
    cudaFuncSetAttribute(gemm_mma_kernel<128, 128, true, __half>,
                         cudaFuncAttributeMaxDynamicSharedMemorySize, smem128);
    cudaFuncSetAttribute(gemm_mma_kernel<128, 64, false, __half>,
                         cudaFuncAttributeMaxDynamicSharedMemorySize, smem64);

    // ---- layer 1: x fp32 [50000,256] -> feat fp16, elr fused
    gemm_mma_kernel<256, 128, true, float><<<gemmGrid, 256, smem128>>>(x, W1, al1, ar1, feat, el, er, n);
    aggregate_kernel<4, 32, true, __half><<<aggGrid, 256>>>(feat, el, er, b1, src, rp, h, n);

    // ---- layer 2: h fp16 -> feat fp16, elr fused
    gemm_mma_kernel<128, 128, true, __half><<<gemmGrid, 256, smem128>>>(h, W2, al2, ar2, feat, el, er, n);
    aggregate_kernel<4, 32, true, __half><<<aggGrid, 256>>>(feat, el, er, b2, src, rp, h, n);

    // ---- layer 3: h fp16 -> feat fp16 (64 wide), elr separate
    gemm_mma_kernel<128, 64, false, __half><<<gemmGrid, 256, smem64>>>(h, W3, nullptr, nullptr, feat, el, er, n);
    elr64_kernel<<<elrGrid1, 256>>>(feat, al3, ar3, el, er, n);
    aggregate_kernel<1, 64, false, float><<<aggGrid, 256>>>(feat, el, er, b3, src, rp, out, n);
}